// round 10
// baseline (speedup 1.0000x reference)
#include <cuda_runtime.h>
#include <math_constants.h>

#define QN 4096
#define VN 2048
#define DN 8192
#define NCHUNK 128   /* row chunks of 32 */
#define RPC 32
#define NBANK 64
#define THRESH 1.5f  /* E[cands/row]=137, sd 11.5; samp<=21 -> fallback ~never */
#define CAP 256
#define GRP 18       /* blocks per group: 1 col + 16 qdl + 1 trip */
#define BS 512

// banks: 0=nce_t2v 1=nce_v2t 2=trip_t2v 3=trip_v2t 4=qdl
// Static zero-init covers run 1; merge's last block resets for graph replays.
// (cand/candCnt/diag are fully overwritten each run -> no reset needed.)
__device__ double   g_bank[5][NBANK];
__device__ float    g_colsum[VN];          // col sum of exp(scores_)
__device__ unsigned g_colkey[VN];          // col max of scores (monotone key)
__device__ float    g_diagS[QN];           // scores [j, j/2]
__device__ float    g_diagS_[QN];          // scores_[j, j/2]
__device__ unsigned g_candCnt[QN];         // per-row candidate count
__device__ float    g_cand[QN * CAP];      // per-row candidates (> THRESH)
__device__ unsigned g_chunkdone[NCHUNK];   // col-pass completion flags
__device__ unsigned g_done;

__device__ __forceinline__ float warpSum(float v) {
    #pragma unroll
    for (int o = 16; o; o >>= 1) v += __shfl_xor_sync(0xffffffffu, v, o);
    return v;
}
__device__ __forceinline__ double warpSumD(double v) {
    #pragma unroll
    for (int o = 16; o; o >>= 1) v += __shfl_xor_sync(0xffffffffu, v, o);
    return v;
}
__device__ __forceinline__ unsigned fkey(float f) {
    unsigned b = __float_as_uint(f);
    return (b & 0x80000000u) ? ~b : (b | 0x80000000u);
}
__device__ __forceinline__ float funkey(unsigned k) {
    return __uint_as_float((k & 0x80000000u) ? (k ^ 0x80000000u) : ~k);
}
// warp (max,count) pair-reduce: returns (m=max, c=count of m) across warp
__device__ __forceinline__ void warpMaxCnt(float& m, int& c) {
    #pragma unroll
    for (int o = 16; o; o >>= 1) {
        float om = __shfl_xor_sync(0xffffffffu, m, o);
        int   oc = __shfl_xor_sync(0xffffffffu, c, o);
        float nm = fmaxf(m, om);
        c = (m == nm ? c : 0) + (om == nm ? oc : 0);
        m = nm;
    }
}

// ===========================================================================
// Fused kernel, 512-thread blocks, grouped by row-chunk:
//   idx 0      : col pass over both matrices (full 2048 cols) + candidates +
//                diag capture + in-block NCE t2v + done-flag
//   idx 1..16  : qdl full-pair blocks (finalized in-block)
//   idx 17     : trip t2v selection from candidates (spin on done-flag)
// ===========================================================================
__global__ void __launch_bounds__(BS) k_fused(
        const float* __restrict__ s, const float* __restrict__ s_,
        const float* __restrict__ qhd, const int* __restrict__ rand_idx) {
    int group = blockIdx.x / GRP;
    int idx   = blockIdx.x % GRP;
    int tid = threadIdx.x;
    int w = tid >> 5, l = tid & 31;

    __shared__ float rowsh[16][RPC];
    __shared__ float diag_sh[RPC];
    __shared__ int   cnt_sh[RPC];
    __shared__ float sh3[3][16];

    if (idx == 0) {
        // ----------------- column pass (one block, 512 threads) -----------------
        int chunk = group;
        int r0 = chunk * RPC;
        int ct = tid;                        // float4 column-tile (0..511)
        int c0 = ct * 4;
        const float4* P_ = (const float4*)(s_ + (size_t)r0 * VN) + ct;
        const float4* P  = (const float4*)(s  + (size_t)r0 * VN) + ct;
        if (tid < RPC) cnt_sh[tid] = 0;
        __syncthreads();
        unsigned lt = (1u << l) - 1u;
        float4 cs = make_float4(0.f, 0.f, 0.f, 0.f);
        float4 cm = make_float4(-CUDART_INF_F, -CUDART_INF_F, -CUDART_INF_F, -CUDART_INF_F);
        #pragma unroll 4
        for (int r = 0; r < RPC; r++) {
            float4 v_ = __ldcs(&P_[(size_t)r * (VN / 4)]);
            float4 v  = __ldcs(&P [(size_t)r * (VN / 4)]);
            float e0 = __expf(v_.x), e1 = __expf(v_.y), e2 = __expf(v_.z), e3 = __expf(v_.w);
            cs.x += e0; cs.y += e1; cs.z += e2; cs.w += e3;
            float rs = warpSum(e0 + e1 + e2 + e3);
            if (l == 0) rowsh[w][r] = rs;
            cm.x = fmaxf(cm.x, v.x); cm.y = fmaxf(cm.y, v.y);
            cm.z = fmaxf(cm.z, v.z); cm.w = fmaxf(cm.w, v.w);
            // candidate capture: warp-aggregated, 1 shared atomic per warp-row
            bool p0 = v.x > THRESH, p1 = v.y > THRESH, p2 = v.z > THRESH, p3 = v.w > THRESH;
            unsigned m0 = __ballot_sync(0xffffffffu, p0);
            unsigned m1 = __ballot_sync(0xffffffffu, p1);
            unsigned m2 = __ballot_sync(0xffffffffu, p2);
            unsigned m3 = __ballot_sync(0xffffffffu, p3);
            int tot = __popc(m0) + __popc(m1) + __popc(m2) + __popc(m3);
            if (tot) {
                int base = 0;
                if (l == 0) base = atomicAdd(&cnt_sh[r], tot);
                base = __shfl_sync(0xffffffffu, base, 0);
                float* dst = &g_cand[(size_t)(r0 + r) * CAP];
                int o0 = base + __popc(m0 & lt);
                if (p0 && o0 < CAP) dst[o0] = v.x;
                int b1 = base + __popc(m0);
                int o1 = b1 + __popc(m1 & lt);
                if (p1 && o1 < CAP) dst[o1] = v.y;
                int b2 = b1 + __popc(m1);
                int o2 = b2 + __popc(m2 & lt);
                if (p2 && o2 < CAP) dst[o2] = v.z;
                int b3 = b2 + __popc(m2);
                int o3 = b3 + __popc(m3 & lt);
                if (p3 && o3 < CAP) dst[o3] = v.w;
            }
        }
        // exclusion fixup + diag capture (4 threads, L1/L2 hits)
        int a0 = chunk * 4;
        if (ct >= a0 && ct < a0 + 4) {
            cm = make_float4(-CUDART_INF_F, -CUDART_INF_F, -CUDART_INF_F, -CUDART_INF_F);
            for (int r = 0; r < RPC; r++) {
                float4 v  = P [(size_t)r * (VN / 4)];
                float4 v_ = P_[(size_t)r * (VN / 4)];
                int row = r0 + r;
                int ex = row >> 1;
                if (ex != c0    ) cm.x = fmaxf(cm.x, v.x);
                else { g_diagS[row] = v.x; g_diagS_[row] = v_.x; diag_sh[r] = v_.x; }
                if (ex != c0 + 1) cm.y = fmaxf(cm.y, v.y);
                else { g_diagS[row] = v.y; g_diagS_[row] = v_.y; diag_sh[r] = v_.y; }
                if (ex != c0 + 2) cm.z = fmaxf(cm.z, v.z);
                else { g_diagS[row] = v.z; g_diagS_[row] = v_.z; diag_sh[r] = v_.z; }
                if (ex != c0 + 3) cm.w = fmaxf(cm.w, v.w);
                else { g_diagS[row] = v.w; g_diagS_[row] = v_.w; diag_sh[r] = v_.w; }
            }
        }
        atomicAdd(&g_colsum[c0    ], cs.x);
        atomicAdd(&g_colsum[c0 + 1], cs.y);
        atomicAdd(&g_colsum[c0 + 2], cs.z);
        atomicAdd(&g_colsum[c0 + 3], cs.w);
        atomicMax(&g_colkey[c0    ], fkey(cm.x));
        atomicMax(&g_colkey[c0 + 1], fkey(cm.y));
        atomicMax(&g_colkey[c0 + 2], fkey(cm.z));
        atomicMax(&g_colkey[c0 + 3], fkey(cm.w));
        __syncthreads();
        if (tid < RPC) g_candCnt[r0 + tid] = (unsigned)cnt_sh[tid];
        // in-block NCE t2v for all 32 rows (warp 0)
        if (w == 0) {
            float rs = 0.f;
            #pragma unroll
            for (int i = 0; i < 16; i++) rs += rowsh[i][l];
            float nce = logf(rs) - diag_sh[l];
            nce = warpSum(nce);
            if (l == 0) atomicAdd(&g_bank[0][chunk & (NBANK - 1)], (double)nce);
        }
        __threadfence();
        __syncthreads();
        if (tid == 0) atomicExch(&g_chunkdone[chunk], 1u);
        return;
    }

    if (idx == GRP - 1) {
        // ----------------- trip t2v: 16 warps x 2 rows, from candidates -----------------
        int okflag = 1;
        if (l == 0) {
            int t = 0;
            while (atomicAdd(&g_chunkdone[group], 0u) == 0u) {
                if (++t > (1 << 22)) { okflag = 0; break; }
            }
        }
        okflag = __shfl_sync(0xffffffffu, okflag, 0);
        __threadfence();
        float hsum = 0.f;
        for (int rr = 0; rr < 2; rr++) {
            int j = group * RPC + 2 * w + rr;
            int samp = 1 + rand_idx[j];       // rank among negatives, 1-indexed
            float ans = 0.f, pos = 0.f;
            bool fast = false;
            if (okflag) {
                pos = g_diagS[j];
                int n = (int)g_candCnt[j];
                bool posAbove = pos > THRESH;
                int nneg = n - (posAbove ? 1 : 0);
                if (n <= CAP && nneg >= samp) {
                    fast = true;
                    float y[8];
                    #pragma unroll
                    for (int k = 0; k < 8; k++)
                        y[k] = (l + 32 * k < n) ? g_cand[(size_t)j * CAP + l + 32 * k]
                                                : -CUDART_INF_F;
                    float thr = CUDART_INF_F;
                    int rank = 1;
                    while (true) {
                        float m = -CUDART_INF_F;
                        #pragma unroll
                        for (int k = 0; k < 8; k++) if (y[k] < thr) m = fmaxf(m, y[k]);
                        int c = 0;
                        #pragma unroll
                        for (int k = 0; k < 8; k++) c += (y[k] == m);
                        warpMaxCnt(m, c);
                        if (posAbove && m == pos) c -= 1;   // drop the positive instance
                        if (rank + c > samp) { ans = m; break; }
                        rank += c;
                        thr = m;
                    }
                }
            }
            if (!fast) {
                // exact fallback: full-row warp scan (essentially never taken)
                const float* row = s + (size_t)j * VN;
                int lab = j >> 1;
                pos = row[lab];
                float thr = CUDART_INF_F;
                int rank = 1;
                while (true) {
                    float m = -CUDART_INF_F;
                    for (int c2 = l; c2 < VN; c2 += 32)
                        if (c2 != lab) { float v = row[c2]; if (v < thr) m = fmaxf(m, v); }
                    int c = 0;
                    for (int c2 = l; c2 < VN; c2 += 32)
                        if (c2 != lab && row[c2] == m) c++;
                    warpMaxCnt(m, c);
                    if (rank + c > samp) { ans = m; break; }
                    rank += c;
                    thr = m;
                }
            }
            hsum += fmaxf(0.f, 0.2f + ans - pos);
        }
        if (l == 0)
            atomicAdd(&g_bank[2][(group * 16 + w) & (NBANK - 1)], (double)hsum);
        return;
    }

    // ----------------- qdl full-pair block (finalized in-block) -----------------
    {
        int pair = group * 16 + (idx - 1);   // 0..2047
        const float4* A = (const float4*)(qhd + (size_t)(2 * pair) * DN);
        const float4* B = A + (DN / 4);
        float sxx = 0.f, syy = 0.f, sxy = 0.f;
        #pragma unroll
        for (int i = 0; i < (DN / 4) / BS; i++) {
            int ii = tid + i * BS;
            float4 a = __ldcs(&A[ii]), b = __ldcs(&B[ii]);
            sxx += a.x * a.x + a.y * a.y + a.z * a.z + a.w * a.w;
            syy += b.x * b.x + b.y * b.y + b.z * b.z + b.w * b.w;
            sxy += a.x * b.x + a.y * b.y + a.z * b.z + a.w * b.w;
        }
        sxx = warpSum(sxx); syy = warpSum(syy); sxy = warpSum(sxy);
        if (l == 0) { sh3[0][w] = sxx; sh3[1][w] = syy; sh3[2][w] = sxy; }
        __syncthreads();
        if (tid == 0) {
            float X = 0.f, Y = 0.f, Z = 0.f;
            #pragma unroll
            for (int i = 0; i < 16; i++) { X += sh3[0][i]; Y += sh3[1][i]; Z += sh3[2][i]; }
            float nx = fmaxf(sqrtf(X), 1e-12f);
            float ny = fmaxf(sqrtf(Y), 1e-12f);
            float c  = Z / (nx * ny);
            float z  = 32.0f * (c + 0.1f);
            float sp = (z > 20.0f) ? z : log1pf(__expf(z));
            atomicAdd(&g_bank[4][pair & (NBANK - 1)], 2.0 * (double)sp);
        }
    }
}

// ===========================================================================
// Merge: per-video column finalization only (8 blocks x 256 = 2048 videos),
// then last-block final combine + state reset.
// ===========================================================================
__global__ void __launch_bounds__(256) k_merge(float* __restrict__ out) {
    int v = blockIdx.x * 256 + threadIdx.x;   // 0..2047
    int l = threadIdx.x & 31;
    {
        float cs = g_colsum[v];
        float cm = funkey(g_colkey[v]);
        float a = g_diagS_[2 * v], b = g_diagS_[2 * v + 1];
        float nce_val = logf(cs) - logf(__expf(a) + __expf(b));
        float ta = g_diagS[2 * v], tb = g_diagS[2 * v + 1];
        float trip_val = fmaxf(0.f, 0.2f + cm - 0.5f * (ta + tb));
        nce_val  = warpSum(nce_val);
        trip_val = warpSum(trip_val);
        if (l == 0) {
            atomicAdd(&g_bank[1][(v >> 5) & (NBANK - 1)], (double)nce_val);
            atomicAdd(&g_bank[3][(v >> 5) & (NBANK - 1)], (double)trip_val);
        }
    }
    // ---- last-block final combine + reset ----
    __threadfence();
    __shared__ int lastb;
    __syncthreads();
    if (threadIdx.x == 0) lastb = (atomicAdd(&g_done, 1u) == gridDim.x - 1);
    __syncthreads();
    if (!lastb) return;
    __threadfence();

    __shared__ double bsum[5];
    int wp = threadIdx.x >> 5;
    if (wp < 5) {
        double vv = g_bank[wp][l] + g_bank[wp][l + 32];
        vv = warpSumD(vv);
        if (l == 0) bsum[wp] = vv;
    }
    __syncthreads();
    if (threadIdx.x == 0) {
        double total = 0.02 * (bsum[0] / QN + bsum[1] / VN)
                     + (bsum[2] / QN + bsum[3] / VN)
                     + 0.04 * (bsum[4] / QN);
        out[0] = (float)total;
    }
    __syncthreads();   // read-out strictly before reset
    for (int i = threadIdx.x; i < 5 * NBANK; i += 256) ((double*)g_bank)[i] = 0.0;
    for (int i = threadIdx.x; i < VN; i += 256) { g_colsum[i] = 0.f; g_colkey[i] = 0u; }
    if (threadIdx.x < NCHUNK) g_chunkdone[threadIdx.x] = 0u;
    if (threadIdx.x == 0) g_done = 0u;
}

extern "C" void kernel_launch(void* const* d_in, const int* in_sizes, int n_in,
                              void* d_out, int out_size) {
    const float* scores   = (const float*)d_in[0];   // hd_similarity_scores  [Q,V]
    const float* scores_  = (const float*)d_in[1];   // hd_similarity_scores_ [Q,V]
    const float* qhd      = (const float*)d_in[2];   // query_hd [Q,D]
    const int*   rand_idx = (const int*)d_in[4];
    float* out = (float*)d_out;

    k_fused<<<NCHUNK * GRP, BS>>>(scores, scores_, qhd, rand_idx);
    k_merge<<<VN / 256, 256>>>(out);
}

// round 11
// speedup vs baseline: 1.0429x; 1.0429x over previous
#include <cuda_runtime.h>
#include <math_constants.h>

#define QN 4096
#define VN 2048
#define DN 8192
#define NCHUNK 128   /* row chunks of 32 for the column pass */
#define RPC 32
#define THRESH 2.0f
#define GRP 66       /* blocks per group: 2 col + 32 trip + 32 qdl */

// Static zero-init covers run 1; the final block resets for graph replays.
// (g_rowp/g_qdlp/g_trip/diag are fully overwritten each run -> no reset.)
__device__ float    g_colsum[VN];        // col sum of exp(scores_)  (atomic add)
__device__ unsigned g_colkey[VN];        // col max of scores (monotone key, atomic max)
__device__ float    g_rowp[2 * QN];      // row partial sums of exp(scores_)
__device__ float    g_qdlp[2 * VN * 3];  // qdl half-pair partials {xx,yy,xy}
__device__ float    g_trip[QN];          // trip t2v per-row hinge
__device__ float    g_diagS[QN];         // scores [j, j/2]
__device__ float    g_diagS_[QN];        // scores_[j, j/2]
__device__ unsigned g_done;              // completion counter

__device__ __forceinline__ float warpSum(float v) {
    #pragma unroll
    for (int o = 16; o; o >>= 1) v += __shfl_xor_sync(0xffffffffu, v, o);
    return v;
}
__device__ __forceinline__ double warpSumD(double v) {
    #pragma unroll
    for (int o = 16; o; o >>= 1) v += __shfl_xor_sync(0xffffffffu, v, o);
    return v;
}
__device__ __forceinline__ unsigned fkey(float f) {
    unsigned b = __float_as_uint(f);
    return (b & 0x80000000u) ? ~b : (b | 0x80000000u);
}
__device__ __forceinline__ float funkey(unsigned k) {
    return __uint_as_float((k & 0x80000000u) ? (k ^ 0x80000000u) : ~k);
}

// ===========================================================================
// Single fused kernel (R9 structure + last-block merge).
// Roles interleaved by row-group so trip rows co-run with the col chunk that
// streams the same scores rows (L2 reuse):
//   idx 0..1   -> col pass (chunk = group, half bx = idx)  [+ diag capture]
//   idx 2..33  -> trip row j = group*32 + idx-2
//   idx 34..65 -> qdl half-pair q = group*32 + idx-34
// Last block to finish performs the full merge + output + state reset.
// ===========================================================================
__global__ void __launch_bounds__(256) k_fused(
        const float* __restrict__ s, const float* __restrict__ s_,
        const float* __restrict__ qhd, const int* __restrict__ rand_idx,
        float* __restrict__ out) {
    int group = blockIdx.x / GRP;
    int idx   = blockIdx.x % GRP;
    int tid = threadIdx.x;
    int w = tid >> 5, l = tid & 31;

    if (idx < 2) {
        // ----------------- column pass -----------------
        int chunk = group, bx = idx;
        int r0 = chunk * RPC;
        int ct = bx * 256 + tid;            // float4 column-tile index (0..511)
        int c0 = ct * 4;
        const float4* P_ = (const float4*)(s_ + (size_t)r0 * VN) + ct;
        const float4* P  = (const float4*)(s  + (size_t)r0 * VN) + ct;
        __shared__ float rowp[8][RPC];
        float4 cs = make_float4(0.f, 0.f, 0.f, 0.f);
        float4 cm = make_float4(-CUDART_INF_F, -CUDART_INF_F, -CUDART_INF_F, -CUDART_INF_F);
        #pragma unroll 4
        for (int r = 0; r < RPC; r++) {
            float4 v_ = __ldcs(&P_[(size_t)r * (VN / 4)]);   // read-once stream
            float4 v  = P [(size_t)r * (VN / 4)];            // keep in L2 for trip role
            float e0 = __expf(v_.x), e1 = __expf(v_.y), e2 = __expf(v_.z), e3 = __expf(v_.w);
            cs.x += e0; cs.y += e1; cs.z += e2; cs.w += e3;
            float rs = warpSum(e0 + e1 + e2 + e3);
            if (l == 0) rowp[w][r] = rs;
            cm.x = fmaxf(cm.x, v.x); cm.y = fmaxf(cm.y, v.y);
            cm.z = fmaxf(cm.z, v.z); cm.w = fmaxf(cm.w, v.w);
        }
        // exclusion fixup + diag capture (4 threads, L1/L2 hits)
        int a0 = chunk * 4;
        if (ct >= a0 && ct < a0 + 4) {
            cm = make_float4(-CUDART_INF_F, -CUDART_INF_F, -CUDART_INF_F, -CUDART_INF_F);
            for (int r = 0; r < RPC; r++) {
                float4 v  = P [(size_t)r * (VN / 4)];
                float4 v_ = P_[(size_t)r * (VN / 4)];
                int row = r0 + r;
                int ex = row >> 1;
                if (ex != c0    ) cm.x = fmaxf(cm.x, v.x); else { g_diagS[row] = v.x; g_diagS_[row] = v_.x; }
                if (ex != c0 + 1) cm.y = fmaxf(cm.y, v.y); else { g_diagS[row] = v.y; g_diagS_[row] = v_.y; }
                if (ex != c0 + 2) cm.z = fmaxf(cm.z, v.z); else { g_diagS[row] = v.z; g_diagS_[row] = v_.z; }
                if (ex != c0 + 3) cm.w = fmaxf(cm.w, v.w); else { g_diagS[row] = v.w; g_diagS_[row] = v_.w; }
            }
        }
        atomicAdd(&g_colsum[c0    ], cs.x);
        atomicAdd(&g_colsum[c0 + 1], cs.y);
        atomicAdd(&g_colsum[c0 + 2], cs.z);
        atomicAdd(&g_colsum[c0 + 3], cs.w);
        atomicMax(&g_colkey[c0    ], fkey(cm.x));
        atomicMax(&g_colkey[c0 + 1], fkey(cm.y));
        atomicMax(&g_colkey[c0 + 2], fkey(cm.z));
        atomicMax(&g_colkey[c0 + 3], fkey(cm.w));
        __syncthreads();
        if (tid < RPC) {
            float t = 0.f;
            #pragma unroll
            for (int i = 0; i < 8; i++) t += rowp[i][tid];
            g_rowp[bx * QN + r0 + tid] = t;
        }
    } else if (idx < 34) {
        // ----------------- trip t2v row selection -----------------
        int j = group * RPC + (idx - 2);
        const float* row = s + (size_t)j * VN;
        int lab = j >> 1;                      // labels[j] = j // 2
        const float4* r4 = (const float4*)row;
        float4 a = r4[tid];
        float4 b = r4[tid + 256];
        float x[8] = { a.x, a.y, a.z, a.w, b.x, b.y, b.z, b.w };
        int base0 = tid * 4, base1 = (tid + 256) * 4;
        #pragma unroll
        for (int i = 0; i < 4; i++) {
            if (base0 + i == lab) x[i]     = -CUDART_INF_F;   // positive (999 @ rank 0)
            if (base1 + i == lab) x[4 + i] = -CUDART_INF_F;
        }
        int samp = 1 + rand_idx[j];            // rank among negatives, 1-indexed
        __shared__ float cand[256];
        __shared__ int   cnt;
        if (tid == 0) cnt = 0;
        __syncthreads();
        #pragma unroll
        for (int i = 0; i < 8; i++) {
            if (x[i] > THRESH) {
                int p = atomicAdd(&cnt, 1);
                if (p < 256) cand[p] = x[i];
            }
        }
        __syncthreads();
        int n = cnt;
        if (n >= samp && n <= 256) {
            if (w == 0) {                      // warp 0 finishes alone; others fall through
                float y[8];
                #pragma unroll
                for (int k = 0; k < 8; k++)
                    y[k] = (l + 32 * k < n) ? cand[l + 32 * k] : -CUDART_INF_F;
                float thr = CUDART_INF_F;
                int rank = 1;
                float ans;
                while (true) {
                    float m = -CUDART_INF_F;
                    #pragma unroll
                    for (int k = 0; k < 8; k++) if (y[k] < thr) m = fmaxf(m, y[k]);
                    int c = 0;
                    #pragma unroll
                    for (int k = 0; k < 8; k++) c += (y[k] == m);
                    #pragma unroll
                    for (int o = 16; o; o >>= 1) {
                        float om = __shfl_xor_sync(0xffffffffu, m, o);
                        int   oc = __shfl_xor_sync(0xffffffffu, c, o);
                        float nm = fmaxf(m, om);
                        c = (m == nm ? c : 0) + (om == nm ? oc : 0);
                        m = nm;
                    }
                    if (rank + c > samp) { ans = m; break; }
                    rank += c;
                    thr = m;
                }
                if (l == 0) g_trip[j] = fmaxf(0.f, 0.2f + ans - row[lab]);
            }
        } else {
            // ---- fallback: exact block-wide iterative selection (rare) ----
            __shared__ float shf[8];
            __shared__ int   shi[8];
            __shared__ float bm;
            __shared__ int   bc;
            float thr = CUDART_INF_F;
            int rank = 1;
            float ans = 0.f;
            while (true) {
                float m = -CUDART_INF_F;
                #pragma unroll
                for (int i = 0; i < 8; i++) if (x[i] < thr) m = fmaxf(m, x[i]);
                int c = 0;
                #pragma unroll
                for (int i = 0; i < 8; i++) c += (x[i] == m);
                #pragma unroll
                for (int o = 16; o; o >>= 1) {
                    float om = __shfl_xor_sync(0xffffffffu, m, o);
                    int   oc = __shfl_xor_sync(0xffffffffu, c, o);
                    float nm = fmaxf(m, om);
                    c = (m == nm ? c : 0) + (om == nm ? oc : 0);
                    m = nm;
                }
                if (l == 0) { shf[w] = m; shi[w] = c; }
                __syncthreads();
                if (tid == 0) {
                    float M = shf[0]; int C = shi[0];
                    #pragma unroll
                    for (int i = 1; i < 8; i++) {
                        float nm = fmaxf(M, shf[i]);
                        C = (M == nm ? C : 0) + (shf[i] == nm ? shi[i] : 0);
                        M = nm;
                    }
                    bm = M; bc = C;
                }
                __syncthreads();
                float m2 = bm; int c2 = bc;
                if (rank + c2 > samp) { ans = m2; break; }
                rank += c2;
                thr = m2;
                __syncthreads();
            }
            if (tid == 0) g_trip[j] = fmaxf(0.f, 0.2f + ans - row[lab]);
        }
    } else {
        // ----------------- qdl half-pair partials -----------------
        int q    = group * RPC + (idx - 34);   // 0..4095
        int pair = q >> 1;
        int half = q & 1;
        const float4* A = (const float4*)(qhd + (size_t)(2 * pair)     * DN + half * (DN / 2));
        const float4* B = (const float4*)(qhd + (size_t)(2 * pair + 1) * DN + half * (DN / 2));
        float sxx = 0.f, syy = 0.f, sxy = 0.f;
        #pragma unroll
        for (int i = 0; i < (DN / 8) / 256; i++) {
            int ii = tid + i * 256;
            float4 a = __ldcs(&A[ii]), b = __ldcs(&B[ii]);
            sxx += a.x * a.x + a.y * a.y + a.z * a.z + a.w * a.w;
            syy += b.x * b.x + b.y * b.y + b.z * b.z + b.w * b.w;
            sxy += a.x * b.x + a.y * b.y + a.z * b.z + a.w * b.w;
        }
        sxx = warpSum(sxx); syy = warpSum(syy); sxy = warpSum(sxy);
        __shared__ float sh[3][8];
        if (l == 0) { sh[0][w] = sxx; sh[1][w] = syy; sh[2][w] = sxy; }
        __syncthreads();
        if (tid == 0) {
            float X = 0.f, Y = 0.f, Z = 0.f;
            #pragma unroll
            for (int i = 0; i < 8; i++) { X += sh[0][i]; Y += sh[1][i]; Z += sh[2][i]; }
            float* dst = &g_qdlp[(size_t)q * 3];
            dst[0] = X; dst[1] = Y; dst[2] = Z;
        }
    }

    // ======================= completion protocol =======================
    __threadfence();
    __shared__ unsigned rank_sh;
    __syncthreads();
    if (tid == 0) rank_sh = atomicAdd(&g_done, 1u);
    __syncthreads();
    if (rank_sh != gridDim.x - 1) return;
    __threadfence();

    // =================== last-block merge (256 threads) ===================
    double a0 = 0.0, a1 = 0.0, a2 = 0.0, a3 = 0.0, a4 = 0.0;
    // rows: NCE t2v + trip pickup (dense, coalesced)
    for (int j = tid; j < QN; j += 256) {
        a0 += (double)(logf(g_rowp[j] + g_rowp[QN + j]) - g_diagS_[j]);
        a2 += (double)g_trip[j];
    }
    // per-video column finalization
    for (int v = tid; v < VN; v += 256) {
        float cs = g_colsum[v];
        float cm = funkey(g_colkey[v]);
        float da = g_diagS_[2 * v], db = g_diagS_[2 * v + 1];
        a1 += (double)(logf(cs) - logf(__expf(da) + __expf(db)));
        float ta = g_diagS[2 * v], tb = g_diagS[2 * v + 1];
        a3 += (double)fmaxf(0.f, 0.2f + cm - 0.5f * (ta + tb));
    }
    // qdl pair finalization
    for (int p = tid; p < VN; p += 256) {
        const float* h0 = &g_qdlp[(size_t)(2 * p) * 3];
        const float* h1 = &g_qdlp[(size_t)(2 * p + 1) * 3];
        float X = h0[0] + h1[0], Y = h0[1] + h1[1], Z = h0[2] + h1[2];
        float nx = fmaxf(sqrtf(X), 1e-12f);
        float ny = fmaxf(sqrtf(Y), 1e-12f);
        float c  = Z / (nx * ny);
        float z  = 32.0f * (c + 0.1f);
        float sp = (z > 20.0f) ? z : log1pf(__expf(z));
        a4 += 2.0 * (double)sp;
    }
    // block reduction of the 5 accumulators
    a0 = warpSumD(a0); a1 = warpSumD(a1); a2 = warpSumD(a2);
    a3 = warpSumD(a3); a4 = warpSumD(a4);
    __shared__ double red[5][8];
    if (l == 0) { red[0][w] = a0; red[1][w] = a1; red[2][w] = a2; red[3][w] = a3; red[4][w] = a4; }
    __syncthreads();
    if (tid == 0) {
        double t0 = 0, t1 = 0, t2 = 0, t3 = 0, t4 = 0;
        #pragma unroll
        for (int i = 0; i < 8; i++) {
            t0 += red[0][i]; t1 += red[1][i]; t2 += red[2][i];
            t3 += red[3][i]; t4 += red[4][i];
        }
        double total = 0.02 * (t0 / QN + t1 / VN)
                     + (t2 / QN + t3 / VN)
                     + 0.04 * (t4 / QN);
        out[0] = (float)total;
    }
    __syncthreads();   // output written strictly before reset
    for (int i = tid; i < VN; i += 256) { g_colsum[i] = 0.f; g_colkey[i] = 0u; }
    if (tid == 0) g_done = 0u;
}

extern "C" void kernel_launch(void* const* d_in, const int* in_sizes, int n_in,
                              void* d_out, int out_size) {
    const float* scores   = (const float*)d_in[0];   // hd_similarity_scores  [Q,V]
    const float* scores_  = (const float*)d_in[1];   // hd_similarity_scores_ [Q,V]
    const float* qhd      = (const float*)d_in[2];   // query_hd [Q,D]
    const int*   rand_idx = (const int*)d_in[4];
    float* out = (float*)d_out;

    k_fused<<<NCHUNK * GRP, 256>>>(scores, scores_, qhd, rand_idx, out);
}

// round 12
// speedup vs baseline: 1.5694x; 1.5048x over previous
#include <cuda_runtime.h>
#include <math_constants.h>

#define QN 4096
#define VN 2048
#define DN 8192
#define NCHUNK 128   /* row chunks of 32 for the column pass */
#define RPC 32
#define NBANK 64
#define THRESH 2.0f
#define GRP 66       /* blocks per group: 2 col + 32 trip + 32 qdl */

// banks: 0=nce_t2v 1=nce_v2t 2=trip_t2v 3=trip_v2t 4=qdl
// Static zero-init covers run 1; merge's last block resets for graph replays.
__device__ double   g_bank[5][NBANK];
__device__ float    g_colsum[VN];        // col sum of exp(scores_)  (atomic add)
__device__ unsigned g_colkey[VN];        // col max of scores (monotone key, atomic max)
__device__ float    g_rowp[2 * QN];      // row partial sums of exp(scores_)
__device__ float    g_qdlp[2 * VN * 3];  // qdl half-pair partials {xx,yy,xy}
__device__ float    g_trip[QN];          // trip t2v per-row hinge
__device__ float    g_diagS[QN];         // scores [j, j/2]
__device__ float    g_diagS_[QN];        // scores_[j, j/2]
__device__ unsigned g_done;

__device__ __forceinline__ float warpSum(float v) {
    #pragma unroll
    for (int o = 16; o; o >>= 1) v += __shfl_xor_sync(0xffffffffu, v, o);
    return v;
}
__device__ __forceinline__ unsigned fkey(float f) {
    unsigned b = __float_as_uint(f);
    return (b & 0x80000000u) ? ~b : (b | 0x80000000u);
}
__device__ __forceinline__ float funkey(unsigned k) {
    return __uint_as_float((k & 0x80000000u) ? (k ^ 0x80000000u) : ~k);
}

// ===========================================================================
// Fused kernel: roles interleaved by row-group so trip rows co-run with the
// col chunk that streams the same scores rows (L2 reuse).
//   idx 0..1   -> col pass (chunk = group, half bx = idx)  [+ diag capture]
//   idx 2..33  -> trip row j = group*32 + idx-2
//   idx 34..65 -> qdl half-pair q = group*32 + idx-34
// ===========================================================================
__global__ void __launch_bounds__(256) k_fused(
        const float* __restrict__ s, const float* __restrict__ s_,
        const float* __restrict__ qhd, const int* __restrict__ rand_idx) {
    int group = blockIdx.x / GRP;
    int idx   = blockIdx.x % GRP;
    int tid = threadIdx.x;
    int w = tid >> 5, l = tid & 31;

    if (idx < 2) {
        // ----------------- column pass -----------------
        int chunk = group, bx = idx;
        int r0 = chunk * RPC;
        int ct = bx * 256 + tid;            // float4 column-tile index (0..511)
        int c0 = ct * 4;
        const float4* P_ = (const float4*)(s_ + (size_t)r0 * VN) + ct;
        const float4* P  = (const float4*)(s  + (size_t)r0 * VN) + ct;
        __shared__ float rowp[8][RPC];
        float4 cs = make_float4(0.f, 0.f, 0.f, 0.f);
        float4 cm = make_float4(-CUDART_INF_F, -CUDART_INF_F, -CUDART_INF_F, -CUDART_INF_F);
        #pragma unroll 4
        for (int r = 0; r < RPC; r++) {
            float4 v_ = __ldcs(&P_[(size_t)r * (VN / 4)]);   // read-once stream
            float4 v  = P [(size_t)r * (VN / 4)];            // keep in L2 for trip role
            float e0 = __expf(v_.x), e1 = __expf(v_.y), e2 = __expf(v_.z), e3 = __expf(v_.w);
            cs.x += e0; cs.y += e1; cs.z += e2; cs.w += e3;
            float rs = warpSum(e0 + e1 + e2 + e3);
            if (l == 0) rowp[w][r] = rs;
            cm.x = fmaxf(cm.x, v.x); cm.y = fmaxf(cm.y, v.y);
            cm.z = fmaxf(cm.z, v.z); cm.w = fmaxf(cm.w, v.w);
        }
        // exclusion fixup + diag capture (4 threads, L1/L2 hits)
        int a0 = chunk * 4;
        if (ct >= a0 && ct < a0 + 4) {
            cm = make_float4(-CUDART_INF_F, -CUDART_INF_F, -CUDART_INF_F, -CUDART_INF_F);
            for (int r = 0; r < RPC; r++) {
                float4 v  = P [(size_t)r * (VN / 4)];
                float4 v_ = P_[(size_t)r * (VN / 4)];
                int row = r0 + r;
                int ex = row >> 1;
                if (ex != c0    ) cm.x = fmaxf(cm.x, v.x); else { g_diagS[row] = v.x; g_diagS_[row] = v_.x; }
                if (ex != c0 + 1) cm.y = fmaxf(cm.y, v.y); else { g_diagS[row] = v.y; g_diagS_[row] = v_.y; }
                if (ex != c0 + 2) cm.z = fmaxf(cm.z, v.z); else { g_diagS[row] = v.z; g_diagS_[row] = v_.z; }
                if (ex != c0 + 3) cm.w = fmaxf(cm.w, v.w); else { g_diagS[row] = v.w; g_diagS_[row] = v_.w; }
            }
        }
        atomicAdd(&g_colsum[c0    ], cs.x);
        atomicAdd(&g_colsum[c0 + 1], cs.y);
        atomicAdd(&g_colsum[c0 + 2], cs.z);
        atomicAdd(&g_colsum[c0 + 3], cs.w);
        atomicMax(&g_colkey[c0    ], fkey(cm.x));
        atomicMax(&g_colkey[c0 + 1], fkey(cm.y));
        atomicMax(&g_colkey[c0 + 2], fkey(cm.z));
        atomicMax(&g_colkey[c0 + 3], fkey(cm.w));
        __syncthreads();
        if (tid < RPC) {
            float t = 0.f;
            #pragma unroll
            for (int i = 0; i < 8; i++) t += rowp[i][tid];
            g_rowp[bx * QN + r0 + tid] = t;
        }
        return;
    }

    if (idx < 34) {
        // ----------------- trip t2v row selection -----------------
        int j = group * RPC + (idx - 2);
        const float* row = s + (size_t)j * VN;
        int lab = j >> 1;                      // labels[j] = j // 2
        const float4* r4 = (const float4*)row;
        float4 a = r4[tid];
        float4 b = r4[tid + 256];
        float x[8] = { a.x, a.y, a.z, a.w, b.x, b.y, b.z, b.w };
        int base0 = tid * 4, base1 = (tid + 256) * 4;
        #pragma unroll
        for (int i = 0; i < 4; i++) {
            if (base0 + i == lab) x[i]     = -CUDART_INF_F;   // positive (999 @ rank 0)
            if (base1 + i == lab) x[4 + i] = -CUDART_INF_F;
        }
        int samp = 1 + rand_idx[j];            // rank among negatives, 1-indexed
        __shared__ float cand[256];
        __shared__ int   cnt;
        if (tid == 0) cnt = 0;
        __syncthreads();
        // ---- ballot-aggregated compaction: 1 shared atomic per warp ----
        {
            unsigned lt = (1u << l) - 1u;
            unsigned msk[8];
            int pre[8];                        // exclusive prefix of popcounts
            int tot = 0;
            #pragma unroll
            for (int i = 0; i < 8; i++) {
                msk[i] = __ballot_sync(0xffffffffu, x[i] > THRESH);
                pre[i] = tot;
                tot += __popc(msk[i]);
            }
            int base = 0;
            if (l == 0 && tot) base = atomicAdd(&cnt, tot);
            base = __shfl_sync(0xffffffffu, base, 0);
            #pragma unroll
            for (int i = 0; i < 8; i++) {
                if (x[i] > THRESH) {
                    int p = base + pre[i] + __popc(msk[i] & lt);
                    if (p < 256) cand[p] = x[i];
                }
            }
        }
        __syncthreads();
        int n = cnt;
        if (n >= samp && n <= 256) {
            if (w != 0) return;                // warp 0 finishes alone
            float y[8];
            #pragma unroll
            for (int k = 0; k < 8; k++)
                y[k] = (l + 32 * k < n) ? cand[l + 32 * k] : -CUDART_INF_F;
            float thr = CUDART_INF_F;
            int rank = 1;
            float ans;
            while (true) {
                float m = -CUDART_INF_F;
                #pragma unroll
                for (int k = 0; k < 8; k++) if (y[k] < thr) m = fmaxf(m, y[k]);
                int c = 0;
                #pragma unroll
                for (int k = 0; k < 8; k++) c += (y[k] == m);
                #pragma unroll
                for (int o = 16; o; o >>= 1) {
                    float om = __shfl_xor_sync(0xffffffffu, m, o);
                    int   oc = __shfl_xor_sync(0xffffffffu, c, o);
                    float nm = fmaxf(m, om);
                    c = (m == nm ? c : 0) + (om == nm ? oc : 0);
                    m = nm;
                }
                if (rank + c > samp) { ans = m; break; }
                rank += c;
                thr = m;
            }
            if (l == 0) g_trip[j] = fmaxf(0.f, 0.2f + ans - row[lab]);
            return;
        }
        // ---- fallback: exact block-wide iterative selection (rare) ----
        __shared__ float shf[8];
        __shared__ int   shi[8];
        __shared__ float bm;
        __shared__ int   bc;
        float thr = CUDART_INF_F;
        int rank = 1;
        float ans = 0.f;
        while (true) {
            float m = -CUDART_INF_F;
            #pragma unroll
            for (int i = 0; i < 8; i++) if (x[i] < thr) m = fmaxf(m, x[i]);
            int c = 0;
            #pragma unroll
            for (int i = 0; i < 8; i++) c += (x[i] == m);
            #pragma unroll
            for (int o = 16; o; o >>= 1) {
                float om = __shfl_xor_sync(0xffffffffu, m, o);
                int   oc = __shfl_xor_sync(0xffffffffu, c, o);
                float nm = fmaxf(m, om);
                c = (m == nm ? c : 0) + (om == nm ? oc : 0);
                m = nm;
            }
            if (l == 0) { shf[w] = m; shi[w] = c; }
            __syncthreads();
            if (tid == 0) {
                float M = shf[0]; int C = shi[0];
                #pragma unroll
                for (int i = 1; i < 8; i++) {
                    float nm = fmaxf(M, shf[i]);
                    C = (M == nm ? C : 0) + (shf[i] == nm ? shi[i] : 0);
                    M = nm;
                }
                bm = M; bc = C;
            }
            __syncthreads();
            float m2 = bm; int c2 = bc;
            if (rank + c2 > samp) { ans = m2; break; }
            rank += c2;
            thr = m2;
            __syncthreads();
        }
        if (tid == 0) g_trip[j] = fmaxf(0.f, 0.2f + ans - row[lab]);
        return;
    }

    // ----------------- qdl half-pair partials -----------------
    {
        int q    = group * RPC + (idx - 34);   // 0..4095
        int pair = q >> 1;
        int half = q & 1;
        const float4* A = (const float4*)(qhd + (size_t)(2 * pair)     * DN + half * (DN / 2));
        const float4* B = (const float4*)(qhd + (size_t)(2 * pair + 1) * DN + half * (DN / 2));
        float sxx = 0.f, syy = 0.f, sxy = 0.f;
        #pragma unroll
        for (int i = 0; i < (DN / 8) / 256; i++) {
            int ii = tid + i * 256;
            float4 a = __ldcs(&A[ii]), b = __ldcs(&B[ii]);
            sxx += a.x * a.x + a.y * a.y + a.z * a.z + a.w * a.w;
            syy += b.x * b.x + b.y * b.y + b.z * b.z + b.w * b.w;
            sxy += a.x * b.x + a.y * b.y + a.z * b.z + a.w * b.w;
        }
        sxx = warpSum(sxx); syy = warpSum(syy); sxy = warpSum(sxy);
        __shared__ float sh[3][8];
        if (l == 0) { sh[0][w] = sxx; sh[1][w] = syy; sh[2][w] = sxy; }
        __syncthreads();
        if (tid == 0) {
            float X = 0.f, Y = 0.f, Z = 0.f;
            #pragma unroll
            for (int i = 0; i < 8; i++) { X += sh[0][i]; Y += sh[1][i]; Z += sh[2][i]; }
            float* dst = &g_qdlp[(size_t)q * 3];
            dst[0] = X; dst[1] = Y; dst[2] = Z;
        }
    }
}

// ===========================================================================
// Merge + final + reset. 32 blocks x 256. All reads dense & coalesced
// (diagonals were captured by the col pass).
//   gid <  4096        : NCE t2v row + trip t2v pickup
//   4096 <= gid < 6144 : per-video column finalization (NCE v2t + trip v2t)
//   6144 <= gid < 8192 : QDL pair finalization
// ===========================================================================
__global__ void k_merge(const int* __restrict__ rand_idx, float* __restrict__ out) {
    int gid = blockIdx.x * 256 + threadIdx.x;
    int l = threadIdx.x & 31;
    if (gid < QN) {
        int j = gid;
        float nce_val = logf(g_rowp[j] + g_rowp[QN + j]) - g_diagS_[j];
        float trip_val = g_trip[j];
        nce_val  = warpSum(nce_val);
        trip_val = warpSum(trip_val);
        if (l == 0) {
            atomicAdd(&g_bank[0][(j >> 5) & (NBANK - 1)], (double)nce_val);
            atomicAdd(&g_bank[2][(j >> 5) & (NBANK - 1)], (double)trip_val);
        }
    } else if (gid < QN + VN) {
        int v = gid - QN;
        float cs = g_colsum[v];
        float cm = funkey(g_colkey[v]);
        float a = g_diagS_[2 * v], b = g_diagS_[2 * v + 1];
        float nce_val = logf(cs) - logf(__expf(a) + __expf(b));
        float ta = g_diagS[2 * v], tb = g_diagS[2 * v + 1];
        float trip_val = fmaxf(0.f, 0.2f + cm - 0.5f * (ta + tb));
        nce_val  = warpSum(nce_val);
        trip_val = warpSum(trip_val);
        if (l == 0) {
            atomicAdd(&g_bank[1][(v >> 5) & (NBANK - 1)], (double)nce_val);
            atomicAdd(&g_bank[3][(v >> 5) & (NBANK - 1)], (double)trip_val);
        }
    } else if (gid < QN + 2 * VN) {
        int p = gid - QN - VN;
        const float* h0 = &g_qdlp[(size_t)(2 * p) * 3];
        const float* h1 = &g_qdlp[(size_t)(2 * p + 1) * 3];
        float X = h0[0] + h1[0], Y = h0[1] + h1[1], Z = h0[2] + h1[2];
        float nx = fmaxf(sqrtf(X), 1e-12f);
        float ny = fmaxf(sqrtf(Y), 1e-12f);
        float c  = Z / (nx * ny);
        float z  = 32.0f * (c + 0.1f);
        float sp = (z > 20.0f) ? z : log1pf(__expf(z));
        sp = warpSum(2.0f * sp);
        if (l == 0) atomicAdd(&g_bank[4][(p >> 5) & (NBANK - 1)], (double)sp);
    }

    // ---- last-block final combine + reset ----
    __threadfence();
    __shared__ int lastb;
    __syncthreads();
    if (threadIdx.x == 0) lastb = (atomicAdd(&g_done, 1u) == gridDim.x - 1);
    __syncthreads();
    if (!lastb) return;
    __threadfence();

    __shared__ double bsum[5];
    int wp = threadIdx.x >> 5;
    if (wp < 5) {
        double v = g_bank[wp][l] + g_bank[wp][l + 32];
        #pragma unroll
        for (int o = 16; o; o >>= 1) v += __shfl_xor_sync(0xffffffffu, v, o);
        if (l == 0) bsum[wp] = v;
    }
    __syncthreads();
    if (threadIdx.x == 0) {
        double total = 0.02 * (bsum[0] / QN + bsum[1] / VN)
                     + (bsum[2] / QN + bsum[3] / VN)
                     + 0.04 * (bsum[4] / QN);
        out[0] = (float)total;
    }
    __syncthreads();   // read-out strictly before reset
    for (int i = threadIdx.x; i < 5 * NBANK; i += 256) ((double*)g_bank)[i] = 0.0;
    for (int i = threadIdx.x; i < VN; i += 256) { g_colsum[i] = 0.f; g_colkey[i] = 0u; }
    if (threadIdx.x == 0) g_done = 0u;
}

extern "C" void kernel_launch(void* const* d_in, const int* in_sizes, int n_in,
                              void* d_out, int out_size) {
    const float* scores   = (const float*)d_in[0];   // hd_similarity_scores  [Q,V]
    const float* scores_  = (const float*)d_in[1];   // hd_similarity_scores_ [Q,V]
    const float* qhd      = (const float*)d_in[2];   // query_hd [Q,D]
    const int*   rand_idx = (const int*)d_in[4];
    float* out = (float*)d_out;

    k_fused<<<NCHUNK * GRP, 256>>>(scores, scores_, qhd, rand_idx);
    k_merge<<<(QN + 2 * VN) / 256, 256>>>(rand_idx, out);
}